// round 15
// baseline (speedup 1.0000x reference)
#include <cuda_runtime.h>
#include <math.h>

// Preisach hysteresis (R13): 2 kernels, NO per-step function table.
//   state row j = prefix of +1 of length c_j, then -1 (within lower triangle).
//   up-step h:   rows with x[j] < h  -> c_j = j+1
//   down-step h: all rows            -> c_j = min(c_j, K), K = #{k: x[k] <= h}
//   b[t] = (sum_j (2*P_j(c_j) - RowTot_j)) / 32896 * scale + offset
// Function encode: SET(v) = 512+v, MIN(m) = m (m <= 511; MIN(511) = identity).
// K1: row prefix sums (blocks 0-15); per-step meta + per-chunk functions
//     g_fv[ci][j] (blocks 16-95). No 2MB g_F materialization.
// K2: split entry scan (threads 0-255: value over chunks [0,40); 256-511:
//     composed function over [40,80)), then one warp per step replays its
//     within-chunk prefix from g_meta/h (ALU only), one Li gather + REDUX.

#define NN 256
#define TT 2000
#define CHUNK 25
#define NCHUNK 80
#define QSCALE 8192.0f

__device__ int g_Li[NN * (NN + 1) / 2 + NN];   // row-local prefix sums (quantized)
__device__ int g_RowTotI[NN];
__device__ int g_meta[TT];                      // -1 up, -2 flat, else K (down)
__device__ int g_fv[NCHUNK * NN];               // [chunk][row] chunk functions

__device__ __forceinline__ float xval(int i) {
    // replicate jnp.linspace(0,1,256) in f32: i * fl(1/255), endpoint exact
    return (i == NN - 1) ? 1.0f : (float)i * (1.0f / 255.0f);
}
__device__ __forceinline__ float softplusf(float v) {
    return fmaxf(v, 0.0f) + log1pf(expf(-fabsf(v)));
}
// K = #{k in [0,256): xval(k) <= hc}; xval weakly monotone -> branchless
// binary search with the identical '<=' predicate (hc<1 on down-steps).
__device__ __forceinline__ int count_le(float hc) {
    int K = 0;
    #pragma unroll
    for (int s = 128; s > 0; s >>= 1) {
        int cand = K + s;
        if (xval(cand - 1) <= hc) K = cand;
    }
    return K;
}
// apply encoded function to a state
__device__ __forceinline__ int fapply(int enc, int c) {
    return (enc >= 512) ? (enc - 512) : min(c, enc);
}

// ---------------- Kernel 1 ----------------
__global__ void __launch_bounds__(512)
k1_build(const float* __restrict__ raw, const float* __restrict__ h) {
    int tid = threadIdx.x;
    if (blockIdx.x < 16) {
        // per-row prefix sums of softplus(raw), one warp per row, MLP=8
        int warp = (blockIdx.x * 512 + tid) >> 5;   // row 0..255
        int lane = tid & 31;
        int j  = warp;
        int sj = j * (j + 1) / 2;
        int oj = sj + j;
        int n  = j + 1;

        int base = lane * 8;
        float v[8];
        #pragma unroll
        for (int k = 0; k < 8; k++) {
            int idx = base + k;
            v[k] = (idx < n) ? raw[sj + idx] : 0.0f;
        }
        int loc[8];
        int run = 0;
        #pragma unroll
        for (int k = 0; k < 8; k++) {
            int idx = base + k;
            int q = (idx < n) ? __float2int_rn(softplusf(v[k]) * QSCALE) : 0;
            run += q;
            loc[k] = run;
        }
        int excl = run;
        #pragma unroll
        for (int d = 1; d < 32; d <<= 1) {
            int t = __shfl_up_sync(0xffffffffu, excl, d);
            if (lane >= d) excl += t;
        }
        excl -= run;

        if (lane == 0) g_Li[oj] = 0;
        #pragma unroll
        for (int k = 0; k < 8; k++) {
            int idx = base + k;
            if (idx < n) g_Li[oj + 1 + idx] = excl + loc[k];
        }
        if (lane == 31) g_RowTotI[j] = excl + run;
    } else {
        // per-step meta + per-(chunk,row) chunk function
        __shared__ int   sm[CHUNK];
        __shared__ float shh[CHUNK];
        int ci = blockIdx.x - 16;
        int j  = tid;
        int t0 = ci * CHUNK;

        if (j < CHUNK) {
            int t = t0 + j;
            float hp = (t == 0) ? 0.0f : h[t - 1];
            float hc = h[t];
            int m;
            if (hc > hp)       m = -1;
            else if (hc < hp)  m = count_le(hc);
            else               m = -2;
            sm[j] = m; shh[j] = hc;
            g_meta[t] = m;
        }
        __syncthreads();
        if (j < NN) {
            float xj = xval(j);
            bool isC = false;
            int vv = 0, m = 511;
            #pragma unroll
            for (int s = 0; s < CHUNK; s++) {
                int mt = sm[s];
                if (mt == -1) {
                    if (xj < shh[s]) { isC = true; vv = j + 1; }
                } else if (mt >= 0) {
                    if (isC) vv = min(vv, mt); else m = min(m, mt);
                }
            }
            g_fv[ci * NN + j] = isC ? (512 + vv) : m;
        }
    }
}

// ---------------- Kernel 2 ----------------
// 125 CTAs x 512 threads. CTA bx handles steps [bx*16, bx*16+16), chunks
// ci0..ci1 (ci1 <= ci0+1). Entry scan split across half-CTAs; each warp then
// replays its within-chunk prefix from meta (ALU only) and gathers Li.
__global__ void __launch_bounds__(512)
k2_emit(const float* __restrict__ h, const float* __restrict__ offset,
        const float* __restrict__ scale, float* __restrict__ out) {
    __shared__ int sA[256];    // value after chunks [0, min(ci0,40))
    __shared__ int sB[256];    // encoded function over chunks [40, ci0)
    __shared__ int stot[16];

    int tid = threadIdx.x;
    int bx  = blockIdx.x;
    int blockBase = bx * 16;
    int ci0 = blockBase / CHUNK;

    // ---- per-warp step/chunk identities + meta prefetch ----
    int wid  = tid >> 5;
    int lane = tid & 31;
    int t  = blockBase + wid;
    int ci = t / CHUNK;
    int t0 = ci * CHUNK;
    int nst = t - t0 + 1;                   // 1..25 steps to replay

    int   myMt = -2;
    float myH  = 0.0f;
    if (lane < CHUNK) { myMt = g_meta[t0 + lane]; myH = h[t0 + lane]; }

    int fc0[8], oj[8];
    float xq[8];
    #pragma unroll
    for (int q = 0; q < 8; q++) {
        int j = lane + 32 * q;
        oj[q]  = j * (j + 3) / 2;
        xq[q]  = xval(j);
        fc0[q] = g_fv[ci0 * NN + j];        // for ci1 entry compose
    }
    int jrow = tid & 255;
    int rt = (tid < 256) ? g_RowTotI[jrow] : 0;

    // ---- split entry scan, full register prefetch (MLP=40) ----
    {
        int base = (tid < 256) ? 0 : 40;
        int fv[40];
        #pragma unroll
        for (int i = 0; i < 40; i++) fv[i] = g_fv[(base + i) * NN + jrow];

        if (tid < 256) {
            int c = 0;
            #pragma unroll
            for (int i = 0; i < 40; i++) {
                int fs = fv[i];
                int nc = fapply(fs, c);
                c = (i < ci0) ? nc : c;
            }
            sA[jrow] = c;
        } else {
            int enc = 511;                  // identity MIN
            #pragma unroll
            for (int i = 0; i < 40; i++) {
                int fs = fv[i];
                int ne = (fs >= 512) ? fs
                       : ((enc >= 512) ? (512 + min(enc - 512, fs))
                                       : min(enc, fs));
                enc = (40 + i < ci0) ? ne : enc;
            }
            sB[jrow] = enc;
        }
    }
    // redundant total reduce (rows counted once by threads 0-255)
    {
        int ws = __reduce_add_sync(0xffffffffu, rt);
        if ((tid & 31) == 0) stot[tid >> 5] = ws;
    }
    __syncthreads();

    int totalI = 0;
    #pragma unroll
    for (int w = 0; w < 16; w++) totalI += stot[w];

    // ---- entries for this warp's chunk ----
    int c[8];
    #pragma unroll
    for (int q = 0; q < 8; q++) {
        int j = lane + 32 * q;
        int e = fapply(sB[j], sA[j]);        // entry(ci0)
        if (ci != ci0) e = fapply(fc0[q], e); // entry(ci0+1)
        c[q] = e;
    }

    // ---- within-chunk replay (ALU only, meta via SHFL broadcast) ----
    for (int u = 0; u < nst; u++) {
        int   mt = __shfl_sync(0xffffffffu, myMt, u);
        float hc = __shfl_sync(0xffffffffu, myH, u);
        if (mt == -1) {
            #pragma unroll
            for (int q = 0; q < 8; q++) {
                int j = lane + 32 * q;
                if (xq[q] < hc) c[q] = j + 1;
            }
        } else if (mt >= 0) {
            #pragma unroll
            for (int q = 0; q < 8; q++) c[q] = min(c[q], mt);
        }
    }

    int rv[8];
    #pragma unroll
    for (int q = 0; q < 8; q++) rv[q] = g_Li[oj[q] + c[q]];   // 8 parallel LDG

    int s8 = ((rv[0] + rv[1]) + (rv[2] + rv[3])) +
             ((rv[4] + rv[5]) + (rv[6] + rv[7]));
    int tot = __reduce_add_sync(0xffffffffu, s8);

    if (lane == 0) {
        float numer = (float)(2 * tot - totalI) * (1.0f / QSCALE);
        out[t] = numer * (1.0f / 32896.0f) * scale[0] + offset[0];
    }
}

extern "C" void kernel_launch(void* const* d_in, const int* in_sizes, int n_in,
                              void* d_out, int out_size) {
    const float* h      = (const float*)d_in[0];
    const float* raw    = (const float*)d_in[1];
    const float* offset = (const float*)d_in[2];
    const float* scale  = (const float*)d_in[3];
    float* out = (float*)d_out;

    k1_build<<<96, 512>>>(raw, h);
    k2_emit<<<125, 512>>>(h, offset, scale, out);
}

// round 16
// speedup vs baseline: 1.1348x; 1.1348x over previous
#include <cuda_runtime.h>
#include <math.h>

// Preisach hysteresis (R15): 2 kernels, no per-step table, spill-free k2.
//   state row j = prefix of +1 of length c_j, then -1 (within lower triangle).
//   up-step h:   rows with x[j] < h  -> c_j = j+1
//   down-step h: all rows            -> c_j = min(c_j, K), K = #{k: x[k] <= h}
//   b[t] = (sum_j (2*P_j(c_j) - RowTot_j)) / 32896 * scale + offset
// Function encode: SET(v) = 512+v, MIN(m) = m (m <= 511; MIN(511) = identity).
// K1: row prefix sums (blocks 0-15); per-step meta + per-chunk functions
//     g_fv[ci][j] (blocks 16-95).
// K2: 125 CTAs x 1024 threads. 4-way split entry scan (20 chunks/thread,
//     seg0 value + seg1-3 functions), smem merge to entries, emit warps
//     replay within-chunk prefix from smem meta, one Li gather + REDUX.

#define NN 256
#define TT 2000
#define CHUNK 25
#define NCHUNK 80
#define QSCALE 8192.0f

__device__ int g_Li[NN * (NN + 1) / 2 + NN];   // row-local prefix sums (quantized)
__device__ int g_RowTotI[NN];
__device__ int g_meta[TT];                      // -1 up, -2 flat, else K (down)
__device__ int g_fv[NCHUNK * NN];               // [chunk][row] chunk functions

__device__ __forceinline__ float xval(int i) {
    // replicate jnp.linspace(0,1,256) in f32: i * fl(1/255), endpoint exact
    return (i == NN - 1) ? 1.0f : (float)i * (1.0f / 255.0f);
}
__device__ __forceinline__ float softplusf(float v) {
    return fmaxf(v, 0.0f) + log1pf(expf(-fabsf(v)));
}
// K = #{k in [0,256): xval(k) <= hc}; xval weakly monotone -> branchless
// binary search with the identical '<=' predicate (hc<1 on down-steps).
__device__ __forceinline__ int count_le(float hc) {
    int K = 0;
    #pragma unroll
    for (int s = 128; s > 0; s >>= 1) {
        int cand = K + s;
        if (xval(cand - 1) <= hc) K = cand;
    }
    return K;
}
// apply encoded function to a state
__device__ __forceinline__ int fapply(int enc, int c) {
    return (enc >= 512) ? (enc - 512) : min(c, enc);
}

// ---------------- Kernel 1 ----------------
__global__ void __launch_bounds__(512)
k1_build(const float* __restrict__ raw, const float* __restrict__ h) {
    int tid = threadIdx.x;
    if (blockIdx.x < 16) {
        // per-row prefix sums of softplus(raw), one warp per row, MLP=8
        int warp = (blockIdx.x * 512 + tid) >> 5;   // row 0..255
        int lane = tid & 31;
        int j  = warp;
        int sj = j * (j + 1) / 2;
        int oj = sj + j;
        int n  = j + 1;

        int base = lane * 8;
        float v[8];
        #pragma unroll
        for (int k = 0; k < 8; k++) {
            int idx = base + k;
            v[k] = (idx < n) ? raw[sj + idx] : 0.0f;
        }
        int loc[8];
        int run = 0;
        #pragma unroll
        for (int k = 0; k < 8; k++) {
            int idx = base + k;
            int q = (idx < n) ? __float2int_rn(softplusf(v[k]) * QSCALE) : 0;
            run += q;
            loc[k] = run;
        }
        int excl = run;
        #pragma unroll
        for (int d = 1; d < 32; d <<= 1) {
            int t = __shfl_up_sync(0xffffffffu, excl, d);
            if (lane >= d) excl += t;
        }
        excl -= run;

        if (lane == 0) g_Li[oj] = 0;
        #pragma unroll
        for (int k = 0; k < 8; k++) {
            int idx = base + k;
            if (idx < n) g_Li[oj + 1 + idx] = excl + loc[k];
        }
        if (lane == 31) g_RowTotI[j] = excl + run;
    } else {
        // per-step meta + per-(chunk,row) chunk function
        __shared__ int   sm[CHUNK];
        __shared__ float shh[CHUNK];
        int ci = blockIdx.x - 16;
        int j  = tid;
        int t0 = ci * CHUNK;

        if (j < CHUNK) {
            int t = t0 + j;
            float hp = (t == 0) ? 0.0f : h[t - 1];
            float hc = h[t];
            int m;
            if (hc > hp)       m = -1;
            else if (hc < hp)  m = count_le(hc);
            else               m = -2;
            sm[j] = m; shh[j] = hc;
            g_meta[t] = m;
        }
        __syncthreads();
        if (j < NN) {
            float xj = xval(j);
            bool isC = false;
            int vv = 0, m = 511;
            #pragma unroll
            for (int s = 0; s < CHUNK; s++) {
                int mt = sm[s];
                if (mt == -1) {
                    if (xj < shh[s]) { isC = true; vv = j + 1; }
                } else if (mt >= 0) {
                    if (isC) vv = min(vv, mt); else m = min(m, mt);
                }
            }
            g_fv[ci * NN + j] = isC ? (512 + vv) : m;
        }
    }
}

// ---------------- Kernel 2 ----------------
// 125 CTAs x 1024 threads. CTA bx handles steps [bx*16, bx*16+16), chunks
// ci0..ci1 (ci1 <= ci0+1).
__global__ void __launch_bounds__(1024)
k2_emit(const float* __restrict__ h, const float* __restrict__ offset,
        const float* __restrict__ scale, float* __restrict__ out) {
    __shared__ int   sV[256], sF1[256], sF2[256], sF3[256];
    __shared__ int   sE0[256], sE1[256];
    __shared__ int   stot[8];
    __shared__ int   smeta[2 * CHUNK];
    __shared__ float shh[2 * CHUNK];

    int tid = threadIdx.x;
    int bx  = blockIdx.x;
    int blockBase = bx * 16;
    int ci0 = blockBase / CHUNK;
    int t0base = ci0 * CHUNK;

    // stage meta/h for this CTA's <=2 chunks
    if (tid < 2 * CHUNK) {
        int tt = t0base + tid;
        if (tt < TT) { smeta[tid] = g_meta[tt]; shh[tid] = h[tt]; }
    }

    // extra chunk-ci0 function for entry(ci0+1) derivation (threads 0-255)
    int gc = 0;
    if (tid < 256) gc = g_fv[ci0 * NN + tid];
    int rt = (tid < 256) ? g_RowTotI[tid] : 0;

    // ---- 4-way split entry scan: seg in {0..3}, 20 chunks each ----
    {
        int seg  = tid >> 8;
        int jrow = tid & 255;
        int base = seg * 20;
        int fv[20];
        #pragma unroll
        for (int i = 0; i < 20; i++) fv[i] = g_fv[(base + i) * NN + jrow];

        if (seg == 0) {
            int c = 0;
            #pragma unroll
            for (int i = 0; i < 20; i++) {
                int nc = fapply(fv[i], c);
                c = (i < ci0) ? nc : c;
            }
            sV[jrow] = c;
        } else {
            int enc = 511;                   // identity MIN
            #pragma unroll
            for (int i = 0; i < 20; i++) {
                int fs = fv[i];
                int ne = (fs >= 512) ? fs
                       : ((enc >= 512) ? (512 + min(enc - 512, fs))
                                       : min(enc, fs));
                enc = (base + i < ci0) ? ne : enc;
            }
            if (seg == 1) sF1[jrow] = enc;
            else if (seg == 2) sF2[jrow] = enc;
            else sF3[jrow] = enc;
        }
    }
    // total reduce (rows counted once by threads 0-255 = warps 0-7)
    {
        int ws = __reduce_add_sync(0xffffffffu, rt);
        if (tid < 256 && (tid & 31) == 0) stot[tid >> 5] = ws;
    }
    __syncthreads();

    // ---- merge to per-row entries (threads 0-255) ----
    if (tid < 256) {
        int e = fapply(sF3[tid], fapply(sF2[tid], fapply(sF1[tid], sV[tid])));
        sE0[tid] = e;
        sE1[tid] = fapply(gc, e);            // entry(ci0+1); unused if same chunk
    }
    __syncthreads();

    // ---- emit: warps 0-15, one warp per output step ----
    if (tid < 512) {
        int wid  = tid >> 5;
        int lane = tid & 31;
        int t  = blockBase + wid;
        int ci = t / CHUNK;
        int t0 = ci * CHUNK;
        int nst = t - t0 + 1;                // 1..25 steps to replay
        int lu0 = (ci - ci0) * CHUNK;

        int totalI = 0;
        #pragma unroll
        for (int w = 0; w < 8; w++) totalI += stot[w];

        const int* E = (ci == ci0) ? sE0 : sE1;
        int c[8], oj[8];
        float xq[8];
        #pragma unroll
        for (int q = 0; q < 8; q++) {
            int j = lane + 32 * q;
            oj[q] = j * (j + 3) / 2;
            xq[q] = xval(j);
            c[q]  = E[j];
        }

        // within-chunk replay, meta broadcast from smem (uniform addresses)
        for (int u = 0; u < nst; u++) {
            int   mt = smeta[lu0 + u];
            float hc = shh[lu0 + u];
            if (mt == -1) {
                #pragma unroll
                for (int q = 0; q < 8; q++) {
                    int j = lane + 32 * q;
                    if (xq[q] < hc) c[q] = j + 1;
                }
            } else if (mt >= 0) {
                #pragma unroll
                for (int q = 0; q < 8; q++) c[q] = min(c[q], mt);
            }
        }

        int rv[8];
        #pragma unroll
        for (int q = 0; q < 8; q++) rv[q] = g_Li[oj[q] + c[q]];  // 8 parallel LDG

        int s8 = ((rv[0] + rv[1]) + (rv[2] + rv[3])) +
                 ((rv[4] + rv[5]) + (rv[6] + rv[7]));
        int tot = __reduce_add_sync(0xffffffffu, s8);

        if (lane == 0) {
            float numer = (float)(2 * tot - totalI) * (1.0f / QSCALE);
            out[t] = numer * (1.0f / 32896.0f) * scale[0] + offset[0];
        }
    }
}

extern "C" void kernel_launch(void* const* d_in, const int* in_sizes, int n_in,
                              void* d_out, int out_size) {
    const float* h      = (const float*)d_in[0];
    const float* raw    = (const float*)d_in[1];
    const float* offset = (const float*)d_in[2];
    const float* scale  = (const float*)d_in[3];
    float* out = (float*)d_out;

    k1_build<<<96, 512>>>(raw, h);
    k2_emit<<<125, 1024>>>(h, offset, scale, out);
}